// round 13
// baseline (speedup 1.0000x reference)
#include <cuda_runtime.h>
#include <cuda.h>
#include <cstdint>

// LIF layer scan: B=64, F=256, L=2048.  out = [z | s], each B*F*L float32.
//
// Warp-specialized barrier-free pipeline, grid=148 (1 CTA/SM), 160 threads:
//   tid 0..127 : scan threads (H=111/110 active), one row each
//   tid 128    : TMA-issue thread (loads + stores + ring bookkeeping)
// R13: input ring deepened to 3 stages (read-ahead = 2 chunks = 57KB/SM) to
// absorb load-completion jitter under high DRAM load. Store ring 2 slots.
// Handshakes: IN_FULL (tx), IN_EMPTY / ST_FULL (count=128), ST_FREE (count=1,
// pre-armed). Balanced rows 111/110 across 148 CTAs; dual tensor maps.
// SMEM tile bases 1024-aligned (TILE_STRIDE=14336) so the SW128 hardware
// swizzle matches the in-kernel quad^(r&7) formula.

#define BB 64
#define FF 256
#define LL 2048
#define CHUNK 64
#define NTH 160
#define NCH (LL / CHUNK)     // 32
#define NBIG 104

#define BETA 15.0f
#define DT 1.0f

#define TILE_STRIDE 14336
#define IN_STG  (2 * TILE_STRIDE)        // 28672 per input stage
#define ST_SLOT (4 * TILE_STRIDE)        // 57344 per store slot
// barrier offsets
#define B_INF(s)  ((s) * 8)              // IN_FULL  x3
#define B_INE(s)  (24 + (s) * 8)         // IN_EMPTY x3
#define B_STF(s)  (48 + (s) * 8)         // ST_FULL  x2
#define B_STE(s)  (64 + (s) * 8)         // ST_FREE  x2
#define IN_OFF  1024
#define ST_OFF  (IN_OFF + 3 * IN_STG)        // 87040 (1024-aligned)
#define SMEM_BYTES (ST_OFF + 2 * ST_SLOT)    // 201728

__device__ __forceinline__ void mbar_init(uint32_t a, uint32_t c) {
    asm volatile("mbarrier.init.shared.b64 [%0], %1;" :: "r"(a), "r"(c) : "memory");
}
__device__ __forceinline__ void mbar_arrive(uint32_t a) {
    asm volatile("mbarrier.arrive.release.cta.shared::cta.b64 _, [%0];"
                 :: "r"(a) : "memory");
}
__device__ __forceinline__ void mbar_expect_tx(uint32_t a, uint32_t bytes) {
    asm volatile("mbarrier.arrive.expect_tx.shared.b64 _, [%0], %1;"
                 :: "r"(a), "r"(bytes) : "memory");
}
__device__ __forceinline__ void mbar_wait(uint32_t a, uint32_t parity) {
    asm volatile(
        "{\n\t.reg .pred P;\n\t"
        "WL_%=:\n\t"
        "mbarrier.try_wait.parity.acquire.cta.shared::cta.b64 P, [%0], %1, 0x989680;\n\t"
        "@P bra.uni WD_%=;\n\t"
        "bra.uni WL_%=;\n\t"
        "WD_%=:\n\t}"
        :: "r"(a), "r"(parity) : "memory");
}
__device__ __forceinline__ void tma_load_2d(uint32_t smem, const CUtensorMap* m,
                                            int x, int y, uint32_t bar) {
    asm volatile(
        "cp.async.bulk.tensor.2d.shared::cta.global.tile.mbarrier::complete_tx::bytes "
        "[%0], [%1, {%2, %3}], [%4];"
        :: "r"(smem), "l"(m), "r"(x), "r"(y), "r"(bar) : "memory");
}
__device__ __forceinline__ void tma_store_2d(const CUtensorMap* m,
                                             int x, int y, uint32_t smem) {
    asm volatile(
        "cp.async.bulk.tensor.2d.global.shared::cta.tile.bulk_group "
        "[%0, {%1, %2}], [%3];"
        :: "l"(m), "r"(x), "r"(y), "r"(smem) : "memory");
}

__global__ __launch_bounds__(NTH, 1)
void lif_tma_kernel(const __grid_constant__ CUtensorMap tin_a,
                    const __grid_constant__ CUtensorMap tin_b,
                    const __grid_constant__ CUtensorMap tz_a,
                    const __grid_constant__ CUtensorMap tz_b,
                    const __grid_constant__ CUtensorMap ts_a,
                    const __grid_constant__ CUtensorMap ts_b,
                    const float* __restrict__ raw_tau,
                    const float* __restrict__ thr_p)
{
    extern __shared__ char smem[];
    uint32_t sb;
    asm("{ .reg .u64 t; cvta.to.shared.u64 t, %1; cvt.u32.u64 %0, t; }"
        : "=r"(sb) : "l"(smem));

    const int tid = threadIdx.x;
    const int bid = blockIdx.x;
    const bool big = (bid < NBIG);
    const int H = big ? 111 : 110;
    const int row0 = big ? bid * 111 : NBIG * 111 + (bid - NBIG) * 110;
    const CUtensorMap* tin = big ? &tin_a : &tin_b;
    const CUtensorMap* tz  = big ? &tz_a  : &tz_b;
    const CUtensorMap* tsm = big ? &ts_a  : &ts_b;
    const uint32_t tx_bytes = (uint32_t)H * 256;

    if (tid == 0) {
        #pragma unroll
        for (int s = 0; s < 3; s++) {
            mbar_init(sb + B_INF(s), 1);
            mbar_init(sb + B_INE(s), 128);
        }
        #pragma unroll
        for (int s = 0; s < 2; s++) {
            mbar_init(sb + B_STF(s), 128);
            mbar_init(sb + B_STE(s), 1);
        }
    }
    __syncthreads();   // barrier init visible; only block-wide sync in kernel

    if (tid < 128) {
        // ===================== scan threads =====================
        const float thr = thr_p[0];
        const bool active = (tid < H);
        float alpha = 0.0f, one_m_alpha = 0.0f;
        if (active) {
            float rt = raw_tau[(row0 + tid) % FF];
            float sp = fmaxf(rt, 0.0f) + log1pf(expf(-fabsf(rt)));
            float tau = sp + 1e-4f;
            alpha = expf(-DT / tau);
            one_m_alpha = 1.0f - alpha;
        }
        const float beta_thr = BETA * thr;
        const int sw = tid & 7;
        const uint32_t rbase = (uint32_t)tid * 128;
        float vv = 0.0f;

        int s3 = 0, q3 = 0;   // input stage idx / parity (mod-3 ring)
        for (int k = 0; k < NCH; k++) {
            const int ss = k & 1;
            const uint32_t ps = (k >> 1) & 1;
            mbar_wait(sb + B_INF(s3), q3);    // input stage ready
            mbar_wait(sb + B_STE(ss), ps);    // store slot drained (pre-armed)

            if (active) {
                const char* ib = smem + IN_OFF + s3 * IN_STG + rbase;
                char* zt = smem + ST_OFF + ss * ST_SLOT + rbase;
                char* st = zt + 2 * TILE_STRIDE;
                #pragma unroll
                for (int tb = 0; tb < 16; tb++) {
                    const uint32_t off = (uint32_t)(tb >> 3) * TILE_STRIDE
                                       + ((uint32_t)((tb & 7) ^ sw) << 4);
                    float4 in4 = *(const float4*)(ib + off);
                    float4 z4, s4;
                    float v_pre; bool spk;
                    v_pre = fmaf(alpha, vv, one_m_alpha * in4.x);
                    z4.x = fmaf(BETA, v_pre, -beta_thr);
                    spk = (v_pre >= thr); s4.x = spk ? 1.0f : 0.0f; vv = spk ? 0.0f : v_pre;
                    v_pre = fmaf(alpha, vv, one_m_alpha * in4.y);
                    z4.y = fmaf(BETA, v_pre, -beta_thr);
                    spk = (v_pre >= thr); s4.y = spk ? 1.0f : 0.0f; vv = spk ? 0.0f : v_pre;
                    v_pre = fmaf(alpha, vv, one_m_alpha * in4.z);
                    z4.z = fmaf(BETA, v_pre, -beta_thr);
                    spk = (v_pre >= thr); s4.z = spk ? 1.0f : 0.0f; vv = spk ? 0.0f : v_pre;
                    v_pre = fmaf(alpha, vv, one_m_alpha * in4.w);
                    z4.w = fmaf(BETA, v_pre, -beta_thr);
                    spk = (v_pre >= thr); s4.w = spk ? 1.0f : 0.0f; vv = spk ? 0.0f : v_pre;
                    *(float4*)(zt + off) = z4;
                    *(float4*)(st + off) = s4;
                }
            }
            mbar_arrive(sb + B_INE(s3));      // input stage consumed
            mbar_arrive(sb + B_STF(ss));      // z/s tiles written
            if (++s3 == 3) { s3 = 0; q3 ^= 1; }
        }
    } else if (tid == 128) {
        // ===================== TMA-issue thread =====================
        mbar_arrive(sb + B_STE(0));           // pre-arm: slots start empty
        mbar_arrive(sb + B_STE(1));
        // prologue: load input stages 0..2
        #pragma unroll
        for (int s = 0; s < 3; s++) {
            mbar_expect_tx(sb + B_INF(s), tx_bytes);
            const uint32_t dst = sb + IN_OFF + s * IN_STG;
            tma_load_2d(dst,               tin, s * CHUNK,      row0, sb + B_INF(s));
            tma_load_2d(dst + TILE_STRIDE, tin, s * CHUNK + 32, row0, sb + B_INF(s));
        }

        int s3 = 0, q3 = 0;   // consumption tracker for refill gating
        for (int k = 0; k < NCH; k++) {
            const int ss = k & 1;
            const uint32_t ps = (k >> 1) & 1;
            // refill stage s3 with chunk k+3 once scan consumed chunk k
            if (k + 3 < NCH) {
                mbar_wait(sb + B_INE(s3), q3);
                mbar_expect_tx(sb + B_INF(s3), tx_bytes);
                const uint32_t dst = sb + IN_OFF + s3 * IN_STG;
                tma_load_2d(dst,               tin, (k + 3) * CHUNK,      row0, sb + B_INF(s3));
                tma_load_2d(dst + TILE_STRIDE, tin, (k + 3) * CHUNK + 32, row0, sb + B_INF(s3));
            }
            // store chunk k from slot ss
            mbar_wait(sb + B_STF(ss), ps);    // tiles written (acquire)
            asm volatile("fence.proxy.async.shared::cta;" ::: "memory");
            const int t0 = k * CHUNK;
            const uint32_t slot = sb + ST_OFF + ss * ST_SLOT;
            tma_store_2d(tz,  t0,      row0, slot);
            tma_store_2d(tz,  t0 + 32, row0, slot + TILE_STRIDE);
            tma_store_2d(tsm, t0,      row0, slot + 2 * TILE_STRIDE);
            tma_store_2d(tsm, t0 + 32, row0, slot + 3 * TILE_STRIDE);
            asm volatile("cp.async.bulk.commit_group;" ::: "memory");
            if (k >= 1) {                      // group k-1 drained -> slot free
                asm volatile("cp.async.bulk.wait_group 1;" ::: "memory");
                mbar_arrive(sb + B_STE(ss ^ 1));
            }
            if (++s3 == 3) { s3 = 0; q3 ^= 1; }
        }
        asm volatile("cp.async.bulk.wait_group 0;" ::: "memory");
    }
}

// ---------------- host side ----------------

typedef CUresult (*EncodeFn)(CUtensorMap*, CUtensorMapDataType, cuuint32_t, void*,
                             const cuuint64_t*, const cuuint64_t*,
                             const cuuint32_t*, const cuuint32_t*,
                             CUtensorMapInterleave, CUtensorMapSwizzle,
                             CUtensorMapL2promotion, CUtensorMapFloatOOBfill);

static void make_map(EncodeFn enc, CUtensorMap* m, void* base, unsigned H) {
    cuuint64_t dims[2]    = {LL, (cuuint64_t)BB * FF};
    cuuint64_t strides[1] = {LL * sizeof(float)};
    cuuint32_t box[2]     = {32, H};
    cuuint32_t es[2]      = {1, 1};
    enc(m, CU_TENSOR_MAP_DATA_TYPE_FLOAT32, 2, base, dims, strides, box, es,
        CU_TENSOR_MAP_INTERLEAVE_NONE, CU_TENSOR_MAP_SWIZZLE_128B,
        CU_TENSOR_MAP_L2_PROMOTION_L2_128B, CU_TENSOR_MAP_FLOAT_OOB_FILL_NONE);
}

extern "C" void kernel_launch(void* const* d_in, const int* in_sizes, int n_in,
                              void* d_out, int out_size)
{
    float* I             = (float*)d_in[0];
    const float* raw_tau = (const float*)d_in[1];
    const float* thr     = (const float*)d_in[2];
    float* out           = (float*)d_out;

    static EncodeFn enc = nullptr;
    if (!enc) {
        cudaDriverEntryPointQueryResult qr;
        void* fp = nullptr;
        cudaGetDriverEntryPoint("cuTensorMapEncodeTiled", &fp,
                                cudaEnableDefault, &qr);
        enc = (EncodeFn)fp;
        cudaFuncSetAttribute(lif_tma_kernel,
                             cudaFuncAttributeMaxDynamicSharedMemorySize, SMEM_BYTES);
    }
    if (!enc) return;

    float* sbase = out + (size_t)BB * FF * LL;
    CUtensorMap in_a, in_b, z_a, z_b, s_a, s_b;
    make_map(enc, &in_a, I, 111);     make_map(enc, &in_b, I, 110);
    make_map(enc, &z_a,  out, 111);   make_map(enc, &z_b,  out, 110);
    make_map(enc, &s_a,  sbase, 111); make_map(enc, &s_b,  sbase, 110);

    lif_tma_kernel<<<148, NTH, SMEM_BYTES>>>(in_a, in_b, z_a, z_b, s_a, s_b,
                                             raw_tau, thr);
}

// round 14
// speedup vs baseline: 1.0589x; 1.0589x over previous
#include <cuda_runtime.h>
#include <cuda.h>
#include <cstdint>

// LIF layer scan: B=64, F=256, L=2048.  out = [z | s], each B*F*L float32.
//
// Warp-specialized barrier-free pipeline, grid=148 (1 CTA/SM), 160 threads:
//   tid 0..127 : scan threads (H=111/110 active), one row each
//   tid 128    : TMA-issue thread (loads + stores + ring bookkeeping)
// R14 = R12 + memory-system hints:
//   - input tensor maps use L2_PROMOTION_L2_256B (merges the two adjacent
//     128B boxes per chunk into one 256B DRAM fetch stream)
//   - evict_first L2 cache-policy hint on all TMA loads and stores
//     (touch-once data; keeps the write stream from thrashing L2)
// Handshakes: IN_FULL (tx), IN_EMPTY / ST_FULL (count=128), ST_FREE (count=1,
// pre-armed). Balanced rows 111/110 over 148 CTAs; dual tensor maps.
// SMEM tile bases 1024-aligned (TILE_STRIDE=14336) so the SW128 hardware
// swizzle matches the in-kernel quad^(r&7) formula.

#define BB 64
#define FF 256
#define LL 2048
#define CHUNK 64
#define NTH 160
#define NCH (LL / CHUNK)     // 32
#define NBIG 104

#define BETA 15.0f
#define DT 1.0f

#define TILE_STRIDE 14336
#define IN_STG  (2 * TILE_STRIDE)
#define ST_SLOT (4 * TILE_STRIDE)
#define B_INF(s)  ((s) * 8)          // IN_FULL
#define B_INE(s)  (16 + (s) * 8)     // IN_EMPTY
#define B_STF(s)  (32 + (s) * 8)     // ST_FULL
#define B_STE(s)  (48 + (s) * 8)     // ST_FREE
#define IN_OFF  1024
#define ST_OFF  (IN_OFF + 2 * IN_STG)       // 58368
#define SMEM_BYTES (ST_OFF + 2 * ST_SLOT)   // 173056

__device__ __forceinline__ void mbar_init(uint32_t a, uint32_t c) {
    asm volatile("mbarrier.init.shared.b64 [%0], %1;" :: "r"(a), "r"(c) : "memory");
}
__device__ __forceinline__ void mbar_arrive(uint32_t a) {
    asm volatile("mbarrier.arrive.release.cta.shared::cta.b64 _, [%0];"
                 :: "r"(a) : "memory");
}
__device__ __forceinline__ void mbar_expect_tx(uint32_t a, uint32_t bytes) {
    asm volatile("mbarrier.arrive.expect_tx.shared.b64 _, [%0], %1;"
                 :: "r"(a), "r"(bytes) : "memory");
}
__device__ __forceinline__ void mbar_wait(uint32_t a, uint32_t parity) {
    asm volatile(
        "{\n\t.reg .pred P;\n\t"
        "WL_%=:\n\t"
        "mbarrier.try_wait.parity.acquire.cta.shared::cta.b64 P, [%0], %1, 0x989680;\n\t"
        "@P bra.uni WD_%=;\n\t"
        "bra.uni WL_%=;\n\t"
        "WD_%=:\n\t}"
        :: "r"(a), "r"(parity) : "memory");
}
__device__ __forceinline__ uint64_t mk_policy_evict_first() {
    uint64_t p;
    asm("createpolicy.fractional.L2::evict_first.b64 %0, 1.0;" : "=l"(p));
    return p;
}
__device__ __forceinline__ void tma_load_2d(uint32_t smem, const CUtensorMap* m,
                                            int x, int y, uint32_t bar, uint64_t pol) {
    asm volatile(
        "cp.async.bulk.tensor.2d.shared::cta.global.tile.mbarrier::complete_tx::bytes"
        ".L2::cache_hint [%0], [%1, {%2, %3}], [%4], %5;"
        :: "r"(smem), "l"(m), "r"(x), "r"(y), "r"(bar), "l"(pol) : "memory");
}
__device__ __forceinline__ void tma_store_2d(const CUtensorMap* m,
                                             int x, int y, uint32_t smem, uint64_t pol) {
    asm volatile(
        "cp.async.bulk.tensor.2d.global.shared::cta.tile.bulk_group"
        ".L2::cache_hint [%0, {%1, %2}], [%3], %4;"
        :: "l"(m), "r"(x), "r"(y), "r"(smem), "l"(pol) : "memory");
}

__global__ __launch_bounds__(NTH, 1)
void lif_tma_kernel(const __grid_constant__ CUtensorMap tin_a,
                    const __grid_constant__ CUtensorMap tin_b,
                    const __grid_constant__ CUtensorMap tz_a,
                    const __grid_constant__ CUtensorMap tz_b,
                    const __grid_constant__ CUtensorMap ts_a,
                    const __grid_constant__ CUtensorMap ts_b,
                    const float* __restrict__ raw_tau,
                    const float* __restrict__ thr_p)
{
    extern __shared__ char smem[];
    uint32_t sb;
    asm("{ .reg .u64 t; cvta.to.shared.u64 t, %1; cvt.u32.u64 %0, t; }"
        : "=r"(sb) : "l"(smem));

    const int tid = threadIdx.x;
    const int bid = blockIdx.x;
    const bool big = (bid < NBIG);
    const int H = big ? 111 : 110;
    const int row0 = big ? bid * 111 : NBIG * 111 + (bid - NBIG) * 110;
    const CUtensorMap* tin = big ? &tin_a : &tin_b;
    const CUtensorMap* tz  = big ? &tz_a  : &tz_b;
    const CUtensorMap* tsm = big ? &ts_a  : &ts_b;
    const uint32_t tx_bytes = (uint32_t)H * 256;

    if (tid == 0) {
        #pragma unroll
        for (int s = 0; s < 2; s++) {
            mbar_init(sb + B_INF(s), 1);
            mbar_init(sb + B_INE(s), 128);
            mbar_init(sb + B_STF(s), 128);
            mbar_init(sb + B_STE(s), 1);
        }
    }
    __syncthreads();   // barrier init visible; only block-wide sync in kernel

    if (tid < 128) {
        // ===================== scan threads =====================
        const float thr = thr_p[0];
        const bool active = (tid < H);
        float alpha = 0.0f, one_m_alpha = 0.0f;
        if (active) {
            float rt = raw_tau[(row0 + tid) % FF];
            float sp = fmaxf(rt, 0.0f) + log1pf(expf(-fabsf(rt)));
            float tau = sp + 1e-4f;
            alpha = expf(-DT / tau);
            one_m_alpha = 1.0f - alpha;
        }
        const float beta_thr = BETA * thr;
        const int sw = tid & 7;
        const uint32_t rbase = (uint32_t)tid * 128;
        float vv = 0.0f;

        for (int k = 0; k < NCH; k++) {
            const int si = k & 1;
            const uint32_t par = (k >> 1) & 1;
            mbar_wait(sb + B_INF(si), par);   // input stage ready
            mbar_wait(sb + B_STE(si), par);   // store slot drained (pre-armed)

            if (active) {
                const char* ib = smem + IN_OFF + si * IN_STG + rbase;
                char* zt = smem + ST_OFF + si * ST_SLOT + rbase;
                char* st = zt + 2 * TILE_STRIDE;
                #pragma unroll
                for (int tb = 0; tb < 16; tb++) {
                    const uint32_t off = (uint32_t)(tb >> 3) * TILE_STRIDE
                                       + ((uint32_t)((tb & 7) ^ sw) << 4);
                    float4 in4 = *(const float4*)(ib + off);
                    float4 z4, s4;
                    float v_pre; bool spk;
                    v_pre = fmaf(alpha, vv, one_m_alpha * in4.x);
                    z4.x = fmaf(BETA, v_pre, -beta_thr);
                    spk = (v_pre >= thr); s4.x = spk ? 1.0f : 0.0f; vv = spk ? 0.0f : v_pre;
                    v_pre = fmaf(alpha, vv, one_m_alpha * in4.y);
                    z4.y = fmaf(BETA, v_pre, -beta_thr);
                    spk = (v_pre >= thr); s4.y = spk ? 1.0f : 0.0f; vv = spk ? 0.0f : v_pre;
                    v_pre = fmaf(alpha, vv, one_m_alpha * in4.z);
                    z4.z = fmaf(BETA, v_pre, -beta_thr);
                    spk = (v_pre >= thr); s4.z = spk ? 1.0f : 0.0f; vv = spk ? 0.0f : v_pre;
                    v_pre = fmaf(alpha, vv, one_m_alpha * in4.w);
                    z4.w = fmaf(BETA, v_pre, -beta_thr);
                    spk = (v_pre >= thr); s4.w = spk ? 1.0f : 0.0f; vv = spk ? 0.0f : v_pre;
                    *(float4*)(zt + off) = z4;
                    *(float4*)(st + off) = s4;
                }
            }
            mbar_arrive(sb + B_INE(si));      // input stage consumed
            mbar_arrive(sb + B_STF(si));      // z/s tiles written
        }
    } else if (tid == 128) {
        // ===================== TMA-issue thread =====================
        const uint64_t pol = mk_policy_evict_first();
        mbar_arrive(sb + B_STE(0));           // pre-arm: slots start empty
        mbar_arrive(sb + B_STE(1));
        // prologue: load input stages 0,1
        #pragma unroll
        for (int s = 0; s < 2; s++) {
            mbar_expect_tx(sb + B_INF(s), tx_bytes);
            const uint32_t dst = sb + IN_OFF + s * IN_STG;
            tma_load_2d(dst,               tin, s * CHUNK,      row0, sb + B_INF(s), pol);
            tma_load_2d(dst + TILE_STRIDE, tin, s * CHUNK + 32, row0, sb + B_INF(s), pol);
        }

        for (int k = 0; k < NCH; k++) {
            const int si = k & 1;
            const uint32_t par = (k >> 1) & 1;
            // refill input stage si with chunk k+2
            if (k + 2 < NCH) {
                mbar_wait(sb + B_INE(si), par);
                mbar_expect_tx(sb + B_INF(si), tx_bytes);
                const uint32_t dst = sb + IN_OFF + si * IN_STG;
                tma_load_2d(dst,               tin, (k + 2) * CHUNK,      row0, sb + B_INF(si), pol);
                tma_load_2d(dst + TILE_STRIDE, tin, (k + 2) * CHUNK + 32, row0, sb + B_INF(si), pol);
            }
            // store chunk k from slot si
            mbar_wait(sb + B_STF(si), par);   // tiles written (acquire)
            asm volatile("fence.proxy.async.shared::cta;" ::: "memory");
            const int t0 = k * CHUNK;
            const uint32_t slot = sb + ST_OFF + si * ST_SLOT;
            tma_store_2d(tz,  t0,      row0, slot,                   pol);
            tma_store_2d(tz,  t0 + 32, row0, slot + TILE_STRIDE,     pol);
            tma_store_2d(tsm, t0,      row0, slot + 2 * TILE_STRIDE, pol);
            tma_store_2d(tsm, t0 + 32, row0, slot + 3 * TILE_STRIDE, pol);
            asm volatile("cp.async.bulk.commit_group;" ::: "memory");
            if (k >= 1) {                     // group k-1 drained -> slot free
                asm volatile("cp.async.bulk.wait_group 1;" ::: "memory");
                mbar_arrive(sb + B_STE(si ^ 1));
            }
        }
        asm volatile("cp.async.bulk.wait_group 0;" ::: "memory");
    }
}

// ---------------- host side ----------------

typedef CUresult (*EncodeFn)(CUtensorMap*, CUtensorMapDataType, cuuint32_t, void*,
                             const cuuint64_t*, const cuuint64_t*,
                             const cuuint32_t*, const cuuint32_t*,
                             CUtensorMapInterleave, CUtensorMapSwizzle,
                             CUtensorMapL2promotion, CUtensorMapFloatOOBfill);

static void make_map(EncodeFn enc, CUtensorMap* m, void* base, unsigned H,
                     CUtensorMapL2promotion promo) {
    cuuint64_t dims[2]    = {LL, (cuuint64_t)BB * FF};
    cuuint64_t strides[1] = {LL * sizeof(float)};
    cuuint32_t box[2]     = {32, H};
    cuuint32_t es[2]      = {1, 1};
    enc(m, CU_TENSOR_MAP_DATA_TYPE_FLOAT32, 2, base, dims, strides, box, es,
        CU_TENSOR_MAP_INTERLEAVE_NONE, CU_TENSOR_MAP_SWIZZLE_128B,
        promo, CU_TENSOR_MAP_FLOAT_OOB_FILL_NONE);
}

extern "C" void kernel_launch(void* const* d_in, const int* in_sizes, int n_in,
                              void* d_out, int out_size)
{
    float* I             = (float*)d_in[0];
    const float* raw_tau = (const float*)d_in[1];
    const float* thr     = (const float*)d_in[2];
    float* out           = (float*)d_out;

    static EncodeFn enc = nullptr;
    if (!enc) {
        cudaDriverEntryPointQueryResult qr;
        void* fp = nullptr;
        cudaGetDriverEntryPoint("cuTensorMapEncodeTiled", &fp,
                                cudaEnableDefault, &qr);
        enc = (EncodeFn)fp;
        cudaFuncSetAttribute(lif_tma_kernel,
                             cudaFuncAttributeMaxDynamicSharedMemorySize, SMEM_BYTES);
    }
    if (!enc) return;

    float* sbase = out + (size_t)BB * FF * LL;
    CUtensorMap in_a, in_b, z_a, z_b, s_a, s_b;
    // input: 256B promotion (merges the two adjacent per-chunk boxes)
    make_map(enc, &in_a, I, 111, CU_TENSOR_MAP_L2_PROMOTION_L2_256B);
    make_map(enc, &in_b, I, 110, CU_TENSOR_MAP_L2_PROMOTION_L2_256B);
    make_map(enc, &z_a,  out, 111, CU_TENSOR_MAP_L2_PROMOTION_L2_128B);
    make_map(enc, &z_b,  out, 110, CU_TENSOR_MAP_L2_PROMOTION_L2_128B);
    make_map(enc, &s_a,  sbase, 111, CU_TENSOR_MAP_L2_PROMOTION_L2_128B);
    make_map(enc, &s_b,  sbase, 110, CU_TENSOR_MAP_L2_PROMOTION_L2_128B);

    lif_tma_kernel<<<148, NTH, SMEM_BYTES>>>(in_a, in_b, z_a, z_b, s_a, s_b,
                                             raw_tau, thr);
}